// round 8
// baseline (speedup 1.0000x reference)
#include <cuda_runtime.h>
#include <cuda_fp16.h>
#include <math.h>
#include <stdint.h>

// Problem constants (fixed shapes per reference)
#define N_D   4096
#define N_M   8192
#define NN    12288          // N_D + N_M
#define EE    196608
#define KHOP  4
#define HIDD  512
#define LDF   2560           // HID*(K+1)

// ---------------- device scratch ------------------------------------------
__device__ int   g_deg[NN];
__device__ float g_norm[NN];
__device__ int   g_offs[NN + 1];
__device__ int   g_cursor[NN];
__device__ int   g_csr_src[EE];
__device__ float g_csr_w[EE];
__device__ float g_h[(size_t)NN * HIDD];                  // [N, 512] fp32
__device__ __half g_Fh[(size_t)NN * LDF];                 // feat, fp16
__device__ __half g_Bt[(size_t)512 * (N_D + N_M + LDF)];  // W^T fp16 (d|m|f)

// ---------------- PTX helpers (plain sm_103-safe) ---------------------------
__device__ __forceinline__ uint32_t smem_u32(const void* p) {
    uint32_t a;
    asm("{ .reg .u64 t; cvta.to.shared.u64 t, %1; cvt.u32.u64 %0, t; }"
        : "=r"(a) : "l"(p));
    return a;
}

__device__ __forceinline__ void cpasync16(uint32_t dst, const void* src) {
    asm volatile("cp.async.cg.shared.global [%0], [%1], 16;" :: "r"(dst), "l"(src));
}
__device__ __forceinline__ void cp_commit() {
    asm volatile("cp.async.commit_group;" ::: "memory");
}
template <int N>
__device__ __forceinline__ void cp_wait() {
    asm volatile("cp.async.wait_group %0;" :: "n"(N) : "memory");
}

__device__ __forceinline__ void ldsm_x4(uint32_t addr, uint32_t& r0, uint32_t& r1,
                                        uint32_t& r2, uint32_t& r3) {
    asm volatile("ldmatrix.sync.aligned.m8n8.x4.shared.b16 {%0,%1,%2,%3}, [%4];"
                 : "=r"(r0), "=r"(r1), "=r"(r2), "=r"(r3) : "r"(addr));
}

__device__ __forceinline__ void mma16816(float* c, const uint32_t* a, const uint32_t* b) {
    asm volatile(
        "mma.sync.aligned.m16n8k16.row.col.f32.f16.f16.f32 "
        "{%0,%1,%2,%3}, {%4,%5,%6,%7}, {%8,%9}, {%0,%1,%2,%3};"
        : "+f"(c[0]), "+f"(c[1]), "+f"(c[2]), "+f"(c[3])
        : "r"(a[0]), "r"(a[1]), "r"(a[2]), "r"(a[3]), "r"(b[0]), "r"(b[1]));
}

__device__ __forceinline__ uint32_t pack2(float a, float b) {
    __half2 h = __floats2half2_rn(a, b);
    return *reinterpret_cast<uint32_t*>(&h);
}

// ---------------- graph-prep kernels ---------------------------------------
__global__ void zero_kernel() {
    int i = blockIdx.x * blockDim.x + threadIdx.x;
    if (i < NN) { g_deg[i] = 0; g_cursor[i] = 0; }
}

__global__ void deg_kernel(const int* __restrict__ dst, int E) {
    int e = blockIdx.x * blockDim.x + threadIdx.x;
    if (e < E) atomicAdd(&g_deg[dst[e]], 1);
}

// fused norm + exclusive scan (single block, warp-shuffle hierarchy)
__global__ __launch_bounds__(1024) void normscan_kernel() {
    int tid = threadIdx.x;
    int lane = tid & 31, wid = tid >> 5;
    int vals[12];
    int base = tid * 12;
    int s = 0;
    #pragma unroll
    for (int j = 0; j < 12; j++) { vals[j] = g_deg[base + j]; s += vals[j]; }
    int x = s;
    #pragma unroll
    for (int o = 1; o < 32; o <<= 1) {
        int y = __shfl_up_sync(0xffffffffu, x, o);
        if (lane >= o) x += y;
    }
    __shared__ int wsum[32];
    if (lane == 31) wsum[wid] = x;
    __syncthreads();
    if (wid == 0) {
        int w = wsum[lane];
        #pragma unroll
        for (int o = 1; o < 32; o <<= 1) {
            int y = __shfl_up_sync(0xffffffffu, w, o);
            if (lane >= o) w += y;
        }
        wsum[lane] = w;
    }
    __syncthreads();
    int run = x - s + (wid ? wsum[wid - 1] : 0);
    #pragma unroll
    for (int j = 0; j < 12; j++) { g_offs[base + j] = run; run += vals[j]; }
    if (tid == 1023) g_offs[NN] = run;
    for (int i = tid; i < NN; i += 1024) {
        int d = g_deg[i];
        g_norm[i] = rsqrtf((float)(d > 0 ? d : 1));
    }
}

__global__ void fill_kernel(const int* __restrict__ src, const int* __restrict__ dst, int E) {
    int e = blockIdx.x * blockDim.x + threadIdx.x;
    if (e < E) {
        int d = dst[e];
        int s = src[e];
        int p = g_offs[d] + atomicAdd(&g_cursor[d], 1);
        g_csr_src[p] = s;
        g_csr_w[p]   = g_norm[s] * g_norm[d];
    }
}

// ---------------- SpMM hop: fp16 gather over CSR, fp32 accumulate ----------
__global__ void hop_kernel(int col_in, int col_out) {
    int v = blockIdx.x;
    int t = threadIdx.x;
    int s0 = g_offs[v], s1 = g_offs[v + 1];
    __shared__ int   s_src[256];
    __shared__ float s_w[256];
    float a0 = 0.f, a1 = 0.f;
    for (int base = s0; base < s1; base += 256) {
        int n = min(256, s1 - base);
        __syncthreads();
        if (t < n) { s_src[t] = g_csr_src[base + t]; s_w[t] = g_csr_w[base + t]; }
        __syncthreads();
        for (int i = 0; i < n; i++) {
            const __half2* row = reinterpret_cast<const __half2*>(
                g_Fh + (size_t)s_src[i] * LDF + col_in);
            float w = s_w[i];
            float2 p = __half22float2(row[t]);
            a0 += w * p.x;
            a1 += w * p.y;
        }
    }
    *reinterpret_cast<__half2*>(g_Fh + (size_t)v * LDF + col_out + 2 * t) =
        __floats2half2_rn(a0, a1);
}

// ---------------- fused weight transpose: Wd|Wm|Wf -> [512,K] fp16 ----------
__global__ void cvtBT_all(const float* __restrict__ Wd, const float* __restrict__ Wm,
                          const float* __restrict__ Wf, __half* __restrict__ o)
{
    const float* W; int K; size_t offs;
    int z = blockIdx.z;
    if (z == 0)      { W = Wd; K = N_D; offs = 0; }
    else if (z == 1) { W = Wm; K = N_M; offs = (size_t)512 * N_D; }
    else             { W = Wf; K = LDF; offs = (size_t)512 * (N_D + N_M); }
    int k0 = blockIdx.y * 32;
    if (k0 >= K) return;

    __shared__ float t[32][33];
    int n0 = blockIdx.x * 32;
    int tx = threadIdx.x, ty = threadIdx.y;  // 32 x 8
    #pragma unroll
    for (int r = 0; r < 32; r += 8)
        t[ty + r][tx] = W[(size_t)(k0 + ty + r) * HIDD + n0 + tx];
    __syncthreads();
    #pragma unroll
    for (int r = 0; r < 32; r += 8)
        o[offs + (size_t)(n0 + ty + r) * K + k0 + tx] = __float2half_rn(t[tx][ty + r]);
}

// ---------------- gemm_dm: fused d+m feature GEMMs --------------------------
// 128x128 tile, 256 threads, 4-stage; A fp32 LDG -> fp16 STS; B via cp.async.
#define GSTAGES 4
#define TILE_B   8192                  // one 128x32 fp16 tile
#define STAGE_DM (2 * TILE_B)          // A, B
#define SMEM_DM  (GSTAGES * STAGE_DM)  // 64 KB

__global__ __launch_bounds__(256, 1) void gemm_dm(
    const float* __restrict__ Ad, const float* __restrict__ Am,
    const __half* __restrict__ Bt)
{
    extern __shared__ char dynsm[];
    const uint32_t sbase = smem_u32(dynsm);

    const int tid = threadIdx.x;
    const int wid = tid >> 5;
    const int lid = tid & 31;
    const int wm  = wid >> 1;
    const int wn  = wid & 1;
    const int by  = blockIdx.y;
    const int nb0 = blockIdx.x * 128;

    const float* A; int K; int crow;
    const __half* bh;
    if (by < 64) {   // m tiles first (longer) for better tail packing
        A = Am + (size_t)by * 128 * N_M; K = N_M; crow = N_D + by * 128;
        bh = Bt + (size_t)512 * N_D;
    } else {
        A = Ad + (size_t)(by - 64) * 128 * N_D; K = N_D; crow = (by - 64) * 128;
        bh = Bt;
    }
    const __half* Bh = bh + (size_t)nb0 * K;
    const int chunks = K >> 5;

    const int arow = tid >> 1, ahalf = tid & 1;
    const float* arp = A + (size_t)arow * K + ahalf * 16;

    auto ldgA = [&](int c, float4* av) {
        const float4* p = reinterpret_cast<const float4*>(arp + (c << 5));
        av[0] = p[0]; av[1] = p[1]; av[2] = p[2]; av[3] = p[3];
    };
    auto stsA = [&](int stage, const float4* av) {
        uint4 u0, u1;
        u0.x = pack2(av[0].x, av[0].y); u0.y = pack2(av[0].z, av[0].w);
        u0.z = pack2(av[1].x, av[1].y); u0.w = pack2(av[1].z, av[1].w);
        u1.x = pack2(av[2].x, av[2].y); u1.y = pack2(av[2].z, av[2].w);
        u1.z = pack2(av[3].x, av[3].y); u1.w = pack2(av[3].z, av[3].w);
        char* p = dynsm + stage * STAGE_DM + arow * 64;
        int ch0 = ahalf * 2;
        int sw  = (arow >> 1) & 3;
        *reinterpret_cast<uint4*>(p + ((ch0 ^ sw) << 4))       = u0;
        *reinterpret_cast<uint4*>(p + (((ch0 + 1) ^ sw) << 4)) = u1;
    };
    auto loadB = [&](int stage, int c) {
        const int k0 = c << 5;
        const uint32_t sb = sbase + stage * STAGE_DM;
        #pragma unroll
        for (int i = 0; i < 2; i++) {
            int idx = tid + (i << 8);
            int row = idx >> 2, ch = idx & 3;
            uint32_t sw = (uint32_t)(ch ^ ((row >> 1) & 3));
            cpasync16(sb + TILE_B + row * 64 + (sw << 4),
                      Bh + (size_t)row * K + k0 + ch * 8);
        }
    };

    float acc[2][8][4] = {};

    #pragma unroll
    for (int s = 0; s < GSTAGES - 1; s++) {
        float4 av[4];
        ldgA(s, av);
        stsA(s, av);
        loadB(s, s);
        cp_commit();
    }

    for (int c = 0; c < chunks; c++) {
        cp_wait<GSTAGES - 2>();
        __syncthreads();
        const int cl = c + GSTAGES - 1;
        const bool dold = (cl < chunks);
        float4 av[4];
        if (dold) { ldgA(cl, av); loadB(cl % GSTAGES, cl); }
        cp_commit();

        const uint32_t sb = sbase + (c % GSTAGES) * STAGE_DM;
        #pragma unroll
        for (int ks = 0; ks < 2; ks++) {
            uint32_t aF[2][4], bF[8][2];
            #pragma unroll
            for (int mt = 0; mt < 2; mt++) {
                int row = wm * 32 + mt * 16 + (lid & 15);
                int ch  = ks * 2 + (lid >> 4);
                uint32_t off = row * 64 + ((uint32_t)(ch ^ ((row >> 1) & 3)) << 4);
                ldsm_x4(sb + off, aF[mt][0], aF[mt][1], aF[mt][2], aF[mt][3]);
            }
            #pragma unroll
            for (int nt2 = 0; nt2 < 4; nt2++) {
                int row = wn * 64 + nt2 * 16 + (lid & 7) + ((lid >> 4) << 3);
                int ch  = ks * 2 + ((lid >> 3) & 1);
                uint32_t off = row * 64 + ((uint32_t)(ch ^ ((row >> 1) & 3)) << 4);
                ldsm_x4(sb + TILE_B + off,
                        bF[2*nt2][0], bF[2*nt2][1], bF[2*nt2+1][0], bF[2*nt2+1][1]);
            }
            #pragma unroll
            for (int mt = 0; mt < 2; mt++)
                #pragma unroll
                for (int nt = 0; nt < 8; nt++)
                    mma16816(acc[mt][nt], aF[mt], bF[nt]);
        }
        if (dold) stsA(cl % GSTAGES, av);
    }

    // ---- epilogue: write fp16 feat only
    const int gid = lid >> 2, tig = lid & 3;
    #pragma unroll
    for (int mt = 0; mt < 2; mt++) {
        #pragma unroll
        for (int nt = 0; nt < 8; nt++) {
            int r0  = crow + wm * 32 + mt * 16 + gid;
            int col = nb0 + wn * 64 + nt * 8 + tig * 2;
            *reinterpret_cast<__half2*>(g_Fh + (size_t)r0 * LDF + col) =
                __floats2half2_rn(acc[mt][nt][0], acc[mt][nt][1]);
            *reinterpret_cast<__half2*>(g_Fh + (size_t)(r0 + 8) * LDF + col) =
                __floats2half2_rn(acc[mt][nt][2], acc[mt][nt][3]);
        }
    }
}

// ---------------- gemm_f: h = feat(fp16) @ Wf + bf --------------------------
// 128x256 tile, 512 threads (16 warps, 4Mx4N), 4-stage cp.async pipeline.
#define TILE_AF  8192                    // 128x32 fp16
#define TILE_BF  16384                   // 256x32 fp16
#define STAGE_F  (TILE_AF + TILE_BF)     // 24 KB
#define SMEM_F   (GSTAGES * STAGE_F)     // 96 KB

__global__ __launch_bounds__(512, 1) void gemm_f(
    const __half* __restrict__ A, const __half* __restrict__ Bt,
    int K, float* __restrict__ C, int ldc, const float* __restrict__ bias)
{
    extern __shared__ char dynsm[];
    const uint32_t sbase = smem_u32(dynsm);

    const int tid = threadIdx.x;
    const int wid = tid >> 5;
    const int lid = tid & 31;
    const int wm  = wid >> 2;          // 0..3
    const int wn  = wid & 3;           // 0..3
    const int mbase = blockIdx.y * 128;
    const int nb0   = blockIdx.x * 256;

    const __half* Ab = A  + (size_t)mbase * K;
    const __half* Bb = Bt + (size_t)nb0 * K;
    const int chunks = K >> 5;

    auto load_stage = [&](int stage, int c) {
        const int k0 = c << 5;
        const uint32_t sb = sbase + stage * STAGE_F;
        {   // A: 128 rows x 64B, 512 threads x 16B = one pass
            int row = tid >> 2, ch = tid & 3;
            uint32_t sw = (uint32_t)(ch ^ ((row >> 1) & 3));
            cpasync16(sb + row * 64 + (sw << 4), Ab + (size_t)row * K + k0 + ch * 8);
        }
        #pragma unroll
        for (int i = 0; i < 2; i++) {   // B: 256 rows x 64B, two passes
            int idx = tid + (i << 9);
            int row = idx >> 2, ch = idx & 3;
            uint32_t sw = (uint32_t)(ch ^ ((row >> 1) & 3));
            cpasync16(sb + TILE_AF + row * 64 + (sw << 4),
                      Bb + (size_t)row * K + k0 + ch * 8);
        }
    };

    float acc[2][8][4] = {};

    #pragma unroll
    for (int s = 0; s < GSTAGES - 1; s++) { load_stage(s, s); cp_commit(); }

    for (int c = 0; c < chunks; c++) {
        cp_wait<GSTAGES - 2>();
        __syncthreads();
        const int cl = c + GSTAGES - 1;
        if (cl < chunks) load_stage(cl % GSTAGES, cl);
        cp_commit();

        const uint32_t sb = sbase + (c % GSTAGES) * STAGE_F;
        #pragma unroll
        for (int ks = 0; ks < 2; ks++) {
            uint32_t aF[2][4], bF[8][2];
            #pragma unroll
            for (int mt = 0; mt < 2; mt++) {
                int row = wm * 32 + mt * 16 + (lid & 15);
                int ch  = ks * 2 + (lid >> 4);
                uint32_t off = row * 64 + ((uint32_t)(ch ^ ((row >> 1) & 3)) << 4);
                ldsm_x4(sb + off, aF[mt][0], aF[mt][1], aF[mt][2], aF[mt][3]);
            }
            #pragma unroll
            for (int nt2 = 0; nt2 < 4; nt2++) {
                int row = wn * 64 + nt2 * 16 + (lid & 7) + ((lid >> 4) << 3);
                int ch  = ks * 2 + ((lid >> 3) & 1);
                uint32_t off = row * 64 + ((uint32_t)(ch ^ ((row >> 1) & 3)) << 4);
                ldsm_x4(sb + TILE_AF + off,
                        bF[2*nt2][0], bF[2*nt2][1], bF[2*nt2+1][0], bF[2*nt2+1][1]);
            }
            #pragma unroll
            for (int mt = 0; mt < 2; mt++)
                #pragma unroll
                for (int nt = 0; nt < 8; nt++)
                    mma16816(acc[mt][nt], aF[mt], bF[nt]);
        }
    }

    const int gid = lid >> 2, tig = lid & 3;
    #pragma unroll
    for (int mt = 0; mt < 2; mt++) {
        #pragma unroll
        for (int nt = 0; nt < 8; nt++) {
            int r0  = mbase + wm * 32 + mt * 16 + gid;
            int col = nb0 + wn * 64 + nt * 8 + tig * 2;
            float2 bb = *reinterpret_cast<const float2*>(bias + col);
            float2 v0 = make_float2(acc[mt][nt][0] + bb.x, acc[mt][nt][1] + bb.y);
            float2 v1 = make_float2(acc[mt][nt][2] + bb.x, acc[mt][nt][3] + bb.y);
            *reinterpret_cast<float2*>(C + (size_t)r0 * ldc + col)       = v0;
            *reinterpret_cast<float2*>(C + (size_t)(r0 + 8) * ldc + col) = v1;
        }
    }
}

// ---------------- pair scoring: warp per pair -------------------------------
__global__ void pair_kernel(const int* __restrict__ dis, const int* __restrict__ mir,
                            const float* __restrict__ Wp, const float* __restrict__ bp,
                            float* __restrict__ out, int P)
{
    int warp = (blockIdx.x * blockDim.x + threadIdx.x) >> 5;
    int lane = threadIdx.x & 31;
    if (warp >= P) return;
    int di = dis[warp];
    int mi = mir[warp];
    const float* hd = g_h + (size_t)di * HIDD;
    const float* hm = g_h + (size_t)mi * HIDD;
    float s = 0.f;
    #pragma unroll 4
    for (int c = lane; c < HIDD; c += 32) {
        float a = hd[c], b = hm[c];
        s += a * Wp[c] + b * Wp[HIDD + c] + (a * b) * Wp[2 * HIDD + c];
    }
    #pragma unroll
    for (int o = 16; o; o >>= 1) s += __shfl_xor_sync(0xffffffffu, s, o);
    if (lane == 0) out[warp] = 1.f / (1.f + expf(-(s + bp[0])));
}

// ---------------- launch ----------------------------------------------------
extern "C" void kernel_launch(void* const* d_in, const int* in_sizes, int n_in,
                              void* d_out, int out_size)
{
    const float* d_sim    = (const float*)d_in[0];
    const float* m_sim    = (const float*)d_in[1];
    const int*   src      = (const int*)  d_in[2];
    const int*   dst      = (const int*)  d_in[3];
    const int*   diseases = (const int*)  d_in[4];
    const int*   mirnas   = (const int*)  d_in[5];
    const float* Wd       = (const float*)d_in[6];
    const float* Wm       = (const float*)d_in[7];
    const float* Wf       = (const float*)d_in[8];
    const float* bf       = (const float*)d_in[9];
    const float* Wp       = (const float*)d_in[10];
    const float* bp       = (const float*)d_in[11];
    float*       out      = (float*)d_out;

    const int E = in_sizes[2];
    const int P = in_sizes[4];

    float* hbuf = nullptr;
    __half *Bt = nullptr, *Fh = nullptr;
    cudaGetSymbolAddress((void**)&hbuf, g_h);
    cudaGetSymbolAddress((void**)&Bt, g_Bt);
    cudaGetSymbolAddress((void**)&Fh, g_Fh);

    cudaFuncSetAttribute(gemm_dm, cudaFuncAttributeMaxDynamicSharedMemorySize, SMEM_DM);
    cudaFuncSetAttribute(gemm_f,  cudaFuncAttributeMaxDynamicSharedMemorySize, SMEM_F);

    // launches ordered so gemm_dm is #4 (the one ncu profiles)
    zero_kernel<<<(NN + 255) / 256, 256>>>();                                   // 1
    deg_kernel<<<(E + 255) / 256, 256>>>(dst, E);                               // 2
    cvtBT_all<<<dim3(HIDD / 32, N_M / 32, 3), dim3(32, 8)>>>(Wd, Wm, Wf, Bt);   // 3
    gemm_dm<<<dim3(4, 96), 256, SMEM_DM>>>(d_sim, m_sim, Bt);                   // 4 <- profiled
    normscan_kernel<<<1, 1024>>>();                                             // 5
    fill_kernel<<<(E + 255) / 256, 256>>>(src, dst, E);                         // 6

    // ---- K hops of normalized gather-sum (fp16 feat, fp32 accumulate)
    for (int hop = 0; hop < KHOP; hop++)
        hop_kernel<<<NN, 256>>>(hop * HIDD, (hop + 1) * HIDD);

    // ---- h = feat @ Wf + bf
    gemm_f<<<dim3(2, 96), 512, SMEM_F>>>(
        Fh, Bt + (size_t)512 * (N_D + N_M), LDF, hbuf, HIDD, bf);

    // ---- pair prediction with sigmoid
    pair_kernel<<<(P * 32 + 255) / 256, 256>>>(diseases, mirnas, Wp, bp, out, P);
    (void)n_in; (void)out_size;
}

// round 9
// speedup vs baseline: 1.0541x; 1.0541x over previous
#include <cuda_runtime.h>
#include <cuda_fp16.h>
#include <math.h>
#include <stdint.h>

// Problem constants (fixed shapes per reference)
#define N_D   4096
#define N_M   8192
#define NN    12288          // N_D + N_M
#define EE    196608
#define KHOP  4
#define HIDD  512
#define LDF   2560           // HID*(K+1)

// ---------------- device scratch ------------------------------------------
__device__ int   g_deg[NN];
__device__ float g_norm[NN];
__device__ int   g_offs[NN + 1];
__device__ int   g_cursor[NN];
__device__ int   g_csr_src[EE];
__device__ float g_csr_w[EE];
__device__ float g_h[(size_t)NN * HIDD];                  // [N, 512] fp32
__device__ __half g_Fh[(size_t)NN * LDF];                 // feat, fp16
__device__ __half g_Bt[(size_t)512 * (N_D + N_M + LDF)];  // W^T fp16 (d|m|f)

// ---------------- PTX helpers (plain sm_103-safe) ---------------------------
__device__ __forceinline__ uint32_t smem_u32(const void* p) {
    uint32_t a;
    asm("{ .reg .u64 t; cvta.to.shared.u64 t, %1; cvt.u32.u64 %0, t; }"
        : "=r"(a) : "l"(p));
    return a;
}

__device__ __forceinline__ void cpasync16(uint32_t dst, const void* src) {
    asm volatile("cp.async.cg.shared.global [%0], [%1], 16;" :: "r"(dst), "l"(src));
}
__device__ __forceinline__ void cp_commit() {
    asm volatile("cp.async.commit_group;" ::: "memory");
}
template <int N>
__device__ __forceinline__ void cp_wait() {
    asm volatile("cp.async.wait_group %0;" :: "n"(N) : "memory");
}

__device__ __forceinline__ void ldsm_x4(uint32_t addr, uint32_t& r0, uint32_t& r1,
                                        uint32_t& r2, uint32_t& r3) {
    asm volatile("ldmatrix.sync.aligned.m8n8.x4.shared.b16 {%0,%1,%2,%3}, [%4];"
                 : "=r"(r0), "=r"(r1), "=r"(r2), "=r"(r3) : "r"(addr));
}

__device__ __forceinline__ void mma16816(float* c, const uint32_t* a, const uint32_t* b) {
    asm volatile(
        "mma.sync.aligned.m16n8k16.row.col.f32.f16.f16.f32 "
        "{%0,%1,%2,%3}, {%4,%5,%6,%7}, {%8,%9}, {%0,%1,%2,%3};"
        : "+f"(c[0]), "+f"(c[1]), "+f"(c[2]), "+f"(c[3])
        : "r"(a[0]), "r"(a[1]), "r"(a[2]), "r"(a[3]), "r"(b[0]), "r"(b[1]));
}

__device__ __forceinline__ uint32_t pack2(float a, float b) {
    __half2 h = __floats2half2_rn(a, b);
    return *reinterpret_cast<uint32_t*>(&h);
}

// ---------------- graph-prep kernels ---------------------------------------
__global__ void zero_kernel() {
    int i = blockIdx.x * blockDim.x + threadIdx.x;
    if (i < NN) { g_deg[i] = 0; g_cursor[i] = 0; }
}

__global__ void deg_kernel(const int* __restrict__ dst, int E) {
    int e = blockIdx.x * blockDim.x + threadIdx.x;
    if (e < E) atomicAdd(&g_deg[dst[e]], 1);
}

// fused norm + exclusive scan (single block, warp-shuffle hierarchy)
__global__ __launch_bounds__(1024) void normscan_kernel() {
    int tid = threadIdx.x;
    int lane = tid & 31, wid = tid >> 5;
    int vals[12];
    int base = tid * 12;
    int s = 0;
    #pragma unroll
    for (int j = 0; j < 12; j++) { vals[j] = g_deg[base + j]; s += vals[j]; }
    int x = s;
    #pragma unroll
    for (int o = 1; o < 32; o <<= 1) {
        int y = __shfl_up_sync(0xffffffffu, x, o);
        if (lane >= o) x += y;
    }
    __shared__ int wsum[32];
    if (lane == 31) wsum[wid] = x;
    __syncthreads();
    if (wid == 0) {
        int w = wsum[lane];
        #pragma unroll
        for (int o = 1; o < 32; o <<= 1) {
            int y = __shfl_up_sync(0xffffffffu, w, o);
            if (lane >= o) w += y;
        }
        wsum[lane] = w;
    }
    __syncthreads();
    int run = x - s + (wid ? wsum[wid - 1] : 0);
    #pragma unroll
    for (int j = 0; j < 12; j++) { g_offs[base + j] = run; run += vals[j]; }
    if (tid == 1023) g_offs[NN] = run;
    for (int i = tid; i < NN; i += 1024) {
        int d = g_deg[i];
        g_norm[i] = rsqrtf((float)(d > 0 ? d : 1));
    }
}

__global__ void fill_kernel(const int* __restrict__ src, const int* __restrict__ dst, int E) {
    int e = blockIdx.x * blockDim.x + threadIdx.x;
    if (e < E) {
        int d = dst[e];
        int s = src[e];
        int p = g_offs[d] + atomicAdd(&g_cursor[d], 1);
        g_csr_src[p] = s;
        g_csr_w[p]   = g_norm[s] * g_norm[d];
    }
}

// ---------------- SpMM hop: fp16 gather over CSR, fp32 accumulate ----------
__global__ void hop_kernel(int col_in, int col_out) {
    int v = blockIdx.x;
    int t = threadIdx.x;
    int s0 = g_offs[v], s1 = g_offs[v + 1];
    __shared__ int   s_src[256];
    __shared__ float s_w[256];
    float a0 = 0.f, a1 = 0.f;
    for (int base = s0; base < s1; base += 256) {
        int n = min(256, s1 - base);
        __syncthreads();
        if (t < n) { s_src[t] = g_csr_src[base + t]; s_w[t] = g_csr_w[base + t]; }
        __syncthreads();
        for (int i = 0; i < n; i++) {
            const __half2* row = reinterpret_cast<const __half2*>(
                g_Fh + (size_t)s_src[i] * LDF + col_in);
            float w = s_w[i];
            float2 p = __half22float2(row[t]);
            a0 += w * p.x;
            a1 += w * p.y;
        }
    }
    *reinterpret_cast<__half2*>(g_Fh + (size_t)v * LDF + col_out + 2 * t) =
        __floats2half2_rn(a0, a1);
}

// ---------------- fused weight transpose: Wd|Wm|Wf -> [512,K] fp16 ----------
__global__ void cvtBT_all(const float* __restrict__ Wd, const float* __restrict__ Wm,
                          const float* __restrict__ Wf, __half* __restrict__ o)
{
    const float* W; int K; size_t offs;
    int z = blockIdx.z;
    if (z == 0)      { W = Wd; K = N_D; offs = 0; }
    else if (z == 1) { W = Wm; K = N_M; offs = (size_t)512 * N_D; }
    else             { W = Wf; K = LDF; offs = (size_t)512 * (N_D + N_M); }
    int k0 = blockIdx.y * 32;
    if (k0 >= K) return;

    __shared__ float t[32][33];
    int n0 = blockIdx.x * 32;
    int tx = threadIdx.x, ty = threadIdx.y;  // 32 x 8
    #pragma unroll
    for (int r = 0; r < 32; r += 8)
        t[ty + r][tx] = W[(size_t)(k0 + ty + r) * HIDD + n0 + tx];
    __syncthreads();
    #pragma unroll
    for (int r = 0; r < 32; r += 8)
        o[offs + (size_t)(n0 + ty + r) * K + k0 + tx] = __float2half_rn(t[tx][ty + r]);
}

// ---------------- shared GEMM core parameters ------------------------------
#define GSTAGES 5
#define TILE_B   8192                  // one 128x32 fp16 tile
#define STAGE_B2 (2 * TILE_B)          // A + B per stage
#define GEMM_SMEM (GSTAGES * STAGE_B2) // 80 KB

// ---------------- gemm_dm: fused d+m feature GEMMs --------------------------
// 128x128 tile, 256 threads, 5-stage; A fp32 LDG -> fp16 STS; B via cp.async.
// Register double-buffered ldmatrix fragments overlap ldsm latency with MMAs.
__global__ __launch_bounds__(256, 1) void gemm_dm(
    const float* __restrict__ Ad, const float* __restrict__ Am,
    const __half* __restrict__ Bt)
{
    extern __shared__ char dynsm[];
    const uint32_t sbase = smem_u32(dynsm);

    const int tid = threadIdx.x;
    const int wid = tid >> 5;
    const int lid = tid & 31;
    const int wm  = wid >> 1;
    const int wn  = wid & 1;
    const int by  = blockIdx.y;
    const int nb0 = blockIdx.x * 128;

    const float* A; int K; int crow;
    const __half* bh;
    if (by < 64) {
        A = Am + (size_t)by * 128 * N_M; K = N_M; crow = N_D + by * 128;
        bh = Bt + (size_t)512 * N_D;
    } else {
        A = Ad + (size_t)(by - 64) * 128 * N_D; K = N_D; crow = (by - 64) * 128;
        bh = Bt;
    }
    const __half* Bh = bh + (size_t)nb0 * K;
    const int chunks = K >> 5;

    const int arow = tid >> 1, ahalf = tid & 1;
    const float* arp = A + (size_t)arow * K + ahalf * 16;

    auto ldgA = [&](int c, float4* av) {
        const float4* p = reinterpret_cast<const float4*>(arp + (c << 5));
        av[0] = p[0]; av[1] = p[1]; av[2] = p[2]; av[3] = p[3];
    };
    auto stsA = [&](int stage, const float4* av) {
        uint4 u0, u1;
        u0.x = pack2(av[0].x, av[0].y); u0.y = pack2(av[0].z, av[0].w);
        u0.z = pack2(av[1].x, av[1].y); u0.w = pack2(av[1].z, av[1].w);
        u1.x = pack2(av[2].x, av[2].y); u1.y = pack2(av[2].z, av[2].w);
        u1.z = pack2(av[3].x, av[3].y); u1.w = pack2(av[3].z, av[3].w);
        char* p = dynsm + stage * STAGE_B2 + arow * 64;
        int ch0 = ahalf * 2;
        int sw  = (arow >> 1) & 3;
        *reinterpret_cast<uint4*>(p + ((ch0 ^ sw) << 4))       = u0;
        *reinterpret_cast<uint4*>(p + (((ch0 + 1) ^ sw) << 4)) = u1;
    };
    auto loadB = [&](int stage, int c) {
        const int k0 = c << 5;
        const uint32_t sb = sbase + stage * STAGE_B2;
        #pragma unroll
        for (int i = 0; i < 2; i++) {
            int idx = tid + (i << 8);
            int row = idx >> 2, ch = idx & 3;
            uint32_t sw = (uint32_t)(ch ^ ((row >> 1) & 3));
            cpasync16(sb + TILE_B + row * 64 + (sw << 4),
                      Bh + (size_t)row * K + k0 + ch * 8);
        }
    };
    auto ldfrags = [&](uint32_t sb, int ks, uint32_t (*aF)[4], uint32_t (*bF)[2]) {
        #pragma unroll
        for (int mt = 0; mt < 2; mt++) {
            int row = wm * 32 + mt * 16 + (lid & 15);
            int ch  = ks * 2 + (lid >> 4);
            uint32_t off = row * 64 + ((uint32_t)(ch ^ ((row >> 1) & 3)) << 4);
            ldsm_x4(sb + off, aF[mt][0], aF[mt][1], aF[mt][2], aF[mt][3]);
        }
        #pragma unroll
        for (int nt2 = 0; nt2 < 4; nt2++) {
            int row = wn * 64 + nt2 * 16 + (lid & 7) + ((lid >> 4) << 3);
            int ch  = ks * 2 + ((lid >> 3) & 1);
            uint32_t off = row * 64 + ((uint32_t)(ch ^ ((row >> 1) & 3)) << 4);
            ldsm_x4(sb + TILE_B + off,
                    bF[2*nt2][0], bF[2*nt2][1], bF[2*nt2+1][0], bF[2*nt2+1][1]);
        }
    };

    float acc[2][8][4] = {};
    uint32_t aF[2][2][4], bF[2][8][2];

    // prologue: fill stages 0..3
    #pragma unroll
    for (int s = 0; s < GSTAGES - 1; s++) {
        float4 av[4];
        ldgA(s, av);
        stsA(s, av);
        loadB(s, s);
        cp_commit();
    }
    cp_wait<2>();             // stages 0,1 ready
    __syncthreads();
    ldfrags(sbase, 0, aF[0], bF[0]);   // (c=0, ks=0)
    int cur = 0;

    for (int c = 0; c < chunks; c++) {
        const int cl = c + GSTAGES - 1;
        const bool dold = (cl < chunks);
        const uint32_t sb_c = sbase + (c % GSTAGES) * STAGE_B2;
        const uint32_t sb_n = sbase + ((c + 1) % GSTAGES) * STAGE_B2;

        float4 av[4];
        if (dold) { ldgA(cl, av); loadB(cl % GSTAGES, cl); }

        // ks=0: prefetch (c,1), mma current
        ldfrags(sb_c, 1, aF[cur ^ 1], bF[cur ^ 1]);
        #pragma unroll
        for (int mt = 0; mt < 2; mt++)
            #pragma unroll
            for (int nt = 0; nt < 8; nt++)
                mma16816(acc[mt][nt], aF[cur][mt], bF[cur][nt]);
        cur ^= 1;

        // ks=1: prefetch (c+1,0) [stage c+1 is ready], mma current
        if (c + 1 < chunks) ldfrags(sb_n, 0, aF[cur ^ 1], bF[cur ^ 1]);
        #pragma unroll
        for (int mt = 0; mt < 2; mt++)
            #pragma unroll
            for (int nt = 0; nt < 8; nt++)
                mma16816(acc[mt][nt], aF[cur][mt], bF[cur][nt]);
        cur ^= 1;

        if (dold) stsA(cl % GSTAGES, av);
        cp_commit();
        cp_wait<2>();
        __syncthreads();
    }

    // ---- epilogue: write fp16 feat only
    const int gid = lid >> 2, tig = lid & 3;
    #pragma unroll
    for (int mt = 0; mt < 2; mt++) {
        #pragma unroll
        for (int nt = 0; nt < 8; nt++) {
            int r0  = crow + wm * 32 + mt * 16 + gid;
            int col = nb0 + wn * 64 + nt * 8 + tig * 2;
            *reinterpret_cast<__half2*>(g_Fh + (size_t)r0 * LDF + col) =
                __floats2half2_rn(acc[mt][nt][0], acc[mt][nt][1]);
            *reinterpret_cast<__half2*>(g_Fh + (size_t)(r0 + 8) * LDF + col) =
                __floats2half2_rn(acc[mt][nt][2], acc[mt][nt][3]);
        }
    }
}

// ---------------- gemm_f: h = feat(fp16) @ Wf + bf --------------------------
// 128x128 tile, 256 threads, 5-stage cp.async, reg double-buffered fragments.
__global__ __launch_bounds__(256, 1) void gemm_f(
    const __half* __restrict__ A, const __half* __restrict__ Bt,
    int K, float* __restrict__ C, int ldc, const float* __restrict__ bias)
{
    extern __shared__ char dynsm[];
    const uint32_t sbase = smem_u32(dynsm);

    const int tid = threadIdx.x;
    const int wid = tid >> 5;
    const int lid = tid & 31;
    const int wm  = wid >> 1;
    const int wn  = wid & 1;
    const int mbase = blockIdx.y * 128;
    const int nb0   = blockIdx.x * 128;

    const __half* gsrc[2] = { A + (size_t)mbase * K, Bt + (size_t)nb0 * K };
    const int chunks = K >> 5;

    auto load_stage = [&](int stage, int c) {
        const int k0 = c << 5;
        const uint32_t sb = sbase + stage * STAGE_B2;
        #pragma unroll
        for (int T = 0; T < 2; T++) {
            #pragma unroll
            for (int i = 0; i < 2; i++) {
                int idx = tid + (i << 8);
                int row = idx >> 2, ch = idx & 3;
                uint32_t sw = (uint32_t)(ch ^ ((row >> 1) & 3));
                cpasync16(sb + T * TILE_B + row * 64 + (sw << 4),
                          gsrc[T] + (size_t)row * K + k0 + ch * 8);
            }
        }
    };
    auto ldfrags = [&](uint32_t sb, int ks, uint32_t (*aF)[4], uint32_t (*bF)[2]) {
        #pragma unroll
        for (int mt = 0; mt < 2; mt++) {
            int row = wm * 32 + mt * 16 + (lid & 15);
            int ch  = ks * 2 + (lid >> 4);
            uint32_t off = row * 64 + ((uint32_t)(ch ^ ((row >> 1) & 3)) << 4);
            ldsm_x4(sb + off, aF[mt][0], aF[mt][1], aF[mt][2], aF[mt][3]);
        }
        #pragma unroll
        for (int nt2 = 0; nt2 < 4; nt2++) {
            int row = wn * 64 + nt2 * 16 + (lid & 7) + ((lid >> 4) << 3);
            int ch  = ks * 2 + ((lid >> 3) & 1);
            uint32_t off = row * 64 + ((uint32_t)(ch ^ ((row >> 1) & 3)) << 4);
            ldsm_x4(sb + TILE_B + off,
                    bF[2*nt2][0], bF[2*nt2][1], bF[2*nt2+1][0], bF[2*nt2+1][1]);
        }
    };

    float acc[2][8][4] = {};
    uint32_t aF[2][2][4], bF[2][8][2];

    #pragma unroll
    for (int s = 0; s < GSTAGES - 1; s++) { load_stage(s, s); cp_commit(); }
    cp_wait<2>();
    __syncthreads();
    ldfrags(sbase, 0, aF[0], bF[0]);
    int cur = 0;

    for (int c = 0; c < chunks; c++) {
        const int cl = c + GSTAGES - 1;
        const uint32_t sb_c = sbase + (c % GSTAGES) * STAGE_B2;
        const uint32_t sb_n = sbase + ((c + 1) % GSTAGES) * STAGE_B2;

        if (cl < chunks) load_stage(cl % GSTAGES, cl);

        ldfrags(sb_c, 1, aF[cur ^ 1], bF[cur ^ 1]);
        #pragma unroll
        for (int mt = 0; mt < 2; mt++)
            #pragma unroll
            for (int nt = 0; nt < 8; nt++)
                mma16816(acc[mt][nt], aF[cur][mt], bF[cur][nt]);
        cur ^= 1;

        if (c + 1 < chunks) ldfrags(sb_n, 0, aF[cur ^ 1], bF[cur ^ 1]);
        #pragma unroll
        for (int mt = 0; mt < 2; mt++)
            #pragma unroll
            for (int nt = 0; nt < 8; nt++)
                mma16816(acc[mt][nt], aF[cur][mt], bF[cur][nt]);
        cur ^= 1;

        cp_commit();
        cp_wait<2>();
        __syncthreads();
    }

    const int gid = lid >> 2, tig = lid & 3;
    #pragma unroll
    for (int mt = 0; mt < 2; mt++) {
        #pragma unroll
        for (int nt = 0; nt < 8; nt++) {
            int r0  = mbase + wm * 32 + mt * 16 + gid;
            int col = nb0 + wn * 64 + nt * 8 + tig * 2;
            float2 bb = *reinterpret_cast<const float2*>(bias + col);
            float2 v0 = make_float2(acc[mt][nt][0] + bb.x, acc[mt][nt][1] + bb.y);
            float2 v1 = make_float2(acc[mt][nt][2] + bb.x, acc[mt][nt][3] + bb.y);
            *reinterpret_cast<float2*>(C + (size_t)r0 * ldc + col)       = v0;
            *reinterpret_cast<float2*>(C + (size_t)(r0 + 8) * ldc + col) = v1;
        }
    }
}

// ---------------- pair scoring: warp per pair -------------------------------
__global__ void pair_kernel(const int* __restrict__ dis, const int* __restrict__ mir,
                            const float* __restrict__ Wp, const float* __restrict__ bp,
                            float* __restrict__ out, int P)
{
    int warp = (blockIdx.x * blockDim.x + threadIdx.x) >> 5;
    int lane = threadIdx.x & 31;
    if (warp >= P) return;
    int di = dis[warp];
    int mi = mir[warp];
    const float* hd = g_h + (size_t)di * HIDD;
    const float* hm = g_h + (size_t)mi * HIDD;
    float s = 0.f;
    #pragma unroll 4
    for (int c = lane; c < HIDD; c += 32) {
        float a = hd[c], b = hm[c];
        s += a * Wp[c] + b * Wp[HIDD + c] + (a * b) * Wp[2 * HIDD + c];
    }
    #pragma unroll
    for (int o = 16; o; o >>= 1) s += __shfl_xor_sync(0xffffffffu, s, o);
    if (lane == 0) out[warp] = 1.f / (1.f + expf(-(s + bp[0])));
}

// ---------------- launch ----------------------------------------------------
extern "C" void kernel_launch(void* const* d_in, const int* in_sizes, int n_in,
                              void* d_out, int out_size)
{
    const float* d_sim    = (const float*)d_in[0];
    const float* m_sim    = (const float*)d_in[1];
    const int*   src      = (const int*)  d_in[2];
    const int*   dst      = (const int*)  d_in[3];
    const int*   diseases = (const int*)  d_in[4];
    const int*   mirnas   = (const int*)  d_in[5];
    const float* Wd       = (const float*)d_in[6];
    const float* Wm       = (const float*)d_in[7];
    const float* Wf       = (const float*)d_in[8];
    const float* bf       = (const float*)d_in[9];
    const float* Wp       = (const float*)d_in[10];
    const float* bp       = (const float*)d_in[11];
    float*       out      = (float*)d_out;

    const int E = in_sizes[2];
    const int P = in_sizes[4];

    float* hbuf = nullptr;
    __half *Bt = nullptr, *Fh = nullptr;
    cudaGetSymbolAddress((void**)&hbuf, g_h);
    cudaGetSymbolAddress((void**)&Bt, g_Bt);
    cudaGetSymbolAddress((void**)&Fh, g_Fh);

    cudaFuncSetAttribute(gemm_dm, cudaFuncAttributeMaxDynamicSharedMemorySize, GEMM_SMEM);
    cudaFuncSetAttribute(gemm_f,  cudaFuncAttributeMaxDynamicSharedMemorySize, GEMM_SMEM);

    // launches ordered so gemm_dm is #4 (the one ncu profiles)
    zero_kernel<<<(NN + 255) / 256, 256>>>();                                   // 1
    deg_kernel<<<(E + 255) / 256, 256>>>(dst, E);                               // 2
    cvtBT_all<<<dim3(HIDD / 32, N_M / 32, 3), dim3(32, 8)>>>(Wd, Wm, Wf, Bt);   // 3
    gemm_dm<<<dim3(4, 96), 256, GEMM_SMEM>>>(d_sim, m_sim, Bt);                 // 4 <- profiled
    normscan_kernel<<<1, 1024>>>();                                             // 5
    fill_kernel<<<(E + 255) / 256, 256>>>(src, dst, E);                         // 6

    // ---- K hops of normalized gather-sum (fp16 feat, fp32 accumulate)
    for (int hop = 0; hop < KHOP; hop++)
        hop_kernel<<<NN, 256>>>(hop * HIDD, (hop + 1) * HIDD);

    // ---- h = feat @ Wf + bf
    gemm_f<<<dim3(4, 96), 256, GEMM_SMEM>>>(
        Fh, Bt + (size_t)512 * (N_D + N_M), LDF, hbuf, HIDD, bf);

    // ---- pair prediction with sigmoid
    pair_kernel<<<(P * 32 + 255) / 256, 256>>>(diseases, mirnas, Wp, bp, out, P);
    (void)n_in; (void)out_size;
}

// round 10
// speedup vs baseline: 1.5687x; 1.4882x over previous
#include <cuda_runtime.h>
#include <cuda_fp16.h>
#include <math.h>
#include <stdint.h>

// Problem constants (fixed shapes per reference)
#define N_D   4096
#define N_M   8192
#define NN    12288          // N_D + N_M
#define EE    196608
#define KHOP  4
#define HIDD  512
#define LDF   2560           // HID*(K+1)

// ---------------- device scratch ------------------------------------------
__device__ int   g_deg[NN];
__device__ float g_norm[NN];
__device__ int   g_offs[NN + 1];
__device__ int   g_cursor[NN];
__device__ int   g_csr_src[EE];
__device__ float g_csr_w[EE];
__device__ float g_h[(size_t)NN * HIDD];                  // [N, 512] fp32
__device__ __half g_Fh[(size_t)NN * LDF];                 // feat, fp16
__device__ __half g_Bt[(size_t)512 * (N_D + N_M + LDF)];  // W^T fp16 (d|m|f)
// fp16 copies of the two similarity matrices: d at 0, m at N_D*N_D
__device__ __half g_Ah[(size_t)N_D * N_D + (size_t)N_M * N_M];

// ---------------- PTX helpers (plain sm_103-safe) ---------------------------
__device__ __forceinline__ uint32_t smem_u32(const void* p) {
    uint32_t a;
    asm("{ .reg .u64 t; cvta.to.shared.u64 t, %1; cvt.u32.u64 %0, t; }"
        : "=r"(a) : "l"(p));
    return a;
}

__device__ __forceinline__ void cpasync16(uint32_t dst, const void* src) {
    asm volatile("cp.async.cg.shared.global [%0], [%1], 16;" :: "r"(dst), "l"(src));
}
__device__ __forceinline__ void cp_commit() {
    asm volatile("cp.async.commit_group;" ::: "memory");
}
template <int N>
__device__ __forceinline__ void cp_wait() {
    asm volatile("cp.async.wait_group %0;" :: "n"(N) : "memory");
}

__device__ __forceinline__ void ldsm_x4(uint32_t addr, uint32_t& r0, uint32_t& r1,
                                        uint32_t& r2, uint32_t& r3) {
    asm volatile("ldmatrix.sync.aligned.m8n8.x4.shared.b16 {%0,%1,%2,%3}, [%4];"
                 : "=r"(r0), "=r"(r1), "=r"(r2), "=r"(r3) : "r"(addr));
}

__device__ __forceinline__ void mma16816(float* c, const uint32_t* a, const uint32_t* b) {
    asm volatile(
        "mma.sync.aligned.m16n8k16.row.col.f32.f16.f16.f32 "
        "{%0,%1,%2,%3}, {%4,%5,%6,%7}, {%8,%9}, {%0,%1,%2,%3};"
        : "+f"(c[0]), "+f"(c[1]), "+f"(c[2]), "+f"(c[3])
        : "r"(a[0]), "r"(a[1]), "r"(a[2]), "r"(a[3]), "r"(b[0]), "r"(b[1]));
}

// ---------------- graph-prep kernels ---------------------------------------
__global__ void zero_kernel() {
    int i = blockIdx.x * blockDim.x + threadIdx.x;
    if (i < NN) { g_deg[i] = 0; g_cursor[i] = 0; }
}

__global__ void deg_kernel(const int* __restrict__ dst, int E) {
    int e = blockIdx.x * blockDim.x + threadIdx.x;
    if (e < E) atomicAdd(&g_deg[dst[e]], 1);
}

// fused norm + exclusive scan (single block, warp-shuffle hierarchy)
__global__ __launch_bounds__(1024) void normscan_kernel() {
    int tid = threadIdx.x;
    int lane = tid & 31, wid = tid >> 5;
    int vals[12];
    int base = tid * 12;
    int s = 0;
    #pragma unroll
    for (int j = 0; j < 12; j++) { vals[j] = g_deg[base + j]; s += vals[j]; }
    int x = s;
    #pragma unroll
    for (int o = 1; o < 32; o <<= 1) {
        int y = __shfl_up_sync(0xffffffffu, x, o);
        if (lane >= o) x += y;
    }
    __shared__ int wsum[32];
    if (lane == 31) wsum[wid] = x;
    __syncthreads();
    if (wid == 0) {
        int w = wsum[lane];
        #pragma unroll
        for (int o = 1; o < 32; o <<= 1) {
            int y = __shfl_up_sync(0xffffffffu, w, o);
            if (lane >= o) w += y;
        }
        wsum[lane] = w;
    }
    __syncthreads();
    int run = x - s + (wid ? wsum[wid - 1] : 0);
    #pragma unroll
    for (int j = 0; j < 12; j++) { g_offs[base + j] = run; run += vals[j]; }
    if (tid == 1023) g_offs[NN] = run;
    for (int i = tid; i < NN; i += 1024) {
        int d = g_deg[i];
        g_norm[i] = rsqrtf((float)(d > 0 ? d : 1));
    }
}

__global__ void fill_kernel(const int* __restrict__ src, const int* __restrict__ dst, int E) {
    int e = blockIdx.x * blockDim.x + threadIdx.x;
    if (e < E) {
        int d = dst[e];
        int s = src[e];
        int p = g_offs[d] + atomicAdd(&g_cursor[d], 1);
        g_csr_src[p] = s;
        g_csr_w[p]   = g_norm[s] * g_norm[d];
    }
}

// ---------------- SpMM hop: fp16 gather over CSR, fp32 accumulate ----------
__global__ void hop_kernel(int col_in, int col_out) {
    int v = blockIdx.x;
    int t = threadIdx.x;
    int s0 = g_offs[v], s1 = g_offs[v + 1];
    __shared__ int   s_src[256];
    __shared__ float s_w[256];
    float a0 = 0.f, a1 = 0.f;
    for (int base = s0; base < s1; base += 256) {
        int n = min(256, s1 - base);
        __syncthreads();
        if (t < n) { s_src[t] = g_csr_src[base + t]; s_w[t] = g_csr_w[base + t]; }
        __syncthreads();
        for (int i = 0; i < n; i++) {
            const __half2* row = reinterpret_cast<const __half2*>(
                g_Fh + (size_t)s_src[i] * LDF + col_in);
            float w = s_w[i];
            float2 p = __half22float2(row[t]);
            a0 += w * p.x;
            a1 += w * p.y;
        }
    }
    *reinterpret_cast<__half2*>(g_Fh + (size_t)v * LDF + col_out + 2 * t) =
        __floats2half2_rn(a0, a1);
}

// ---------------- fp32 -> fp16 convert (row-major copy) --------------------
__global__ void cvtA_kernel(const float* __restrict__ A,
                            __half* __restrict__ out, int n4)
{
    int i = blockIdx.x * blockDim.x + threadIdx.x;
    if (i >= n4) return;
    float4 v = reinterpret_cast<const float4*>(A)[i];
    uint2 p;
    __half2* hp = reinterpret_cast<__half2*>(&p);
    hp[0] = __floats2half2_rn(v.x, v.y);
    hp[1] = __floats2half2_rn(v.z, v.w);
    reinterpret_cast<uint2*>(out)[i] = p;
}

// ---------------- fused weight transpose: Wd|Wm|Wf -> [512,K] fp16 ----------
__global__ void cvtBT_all(const float* __restrict__ Wd, const float* __restrict__ Wm,
                          const float* __restrict__ Wf, __half* __restrict__ o)
{
    const float* W; int K; size_t offs;
    int z = blockIdx.z;
    if (z == 0)      { W = Wd; K = N_D; offs = 0; }
    else if (z == 1) { W = Wm; K = N_M; offs = (size_t)512 * N_D; }
    else             { W = Wf; K = LDF; offs = (size_t)512 * (N_D + N_M); }
    int k0 = blockIdx.y * 32;
    if (k0 >= K) return;

    __shared__ float t[32][33];
    int n0 = blockIdx.x * 32;
    int tx = threadIdx.x, ty = threadIdx.y;  // 32 x 8
    #pragma unroll
    for (int r = 0; r < 32; r += 8)
        t[ty + r][tx] = W[(size_t)(k0 + ty + r) * HIDD + n0 + tx];
    __syncthreads();
    #pragma unroll
    for (int r = 0; r < 32; r += 8)
        o[offs + (size_t)(n0 + ty + r) * K + k0 + tx] = __float2half_rn(t[tx][ty + r]);
}

// ---------------- fp16 HMMA GEMM core ---------------------------------------
// 128x128 tile, 256 threads, 4-stage cp.async (A fp16 + B fp16), single-buffer
// fragments, __launch_bounds__(256,2) -> 2 CTAs/SM (16 warps) for latency hiding.
#define GSTG 4
#define TILE_B   8192                  // one 128x32 fp16 tile
#define STAGE_B2 (2 * TILE_B)          // A + B per stage = 16 KB
#define GEMM_SMEM (GSTG * STAGE_B2)    // 64 KB

// mode 0: fused d/m (A from g_Ah, by<64 -> m, else d; fp16 out to g_Fh)
// mode 1: f (A, B, K from args; fp32 out to C with bias)
__global__ __launch_bounds__(256, 2) void gemm_core(
    const __half* __restrict__ Aall, const __half* __restrict__ Bt,
    int Kin, float* __restrict__ C, const float* __restrict__ bias, int mode)
{
    extern __shared__ char dynsm[];
    const uint32_t sbase = smem_u32(dynsm);

    const int tid = threadIdx.x;
    const int wid = tid >> 5;
    const int lid = tid & 31;
    const int wm  = wid >> 1;
    const int wn  = wid & 1;
    const int by  = blockIdx.y;
    const int nb0 = blockIdx.x * 128;

    const __half* A; const __half* Bh; int K; int crow;
    if (mode == 0) {
        if (by < 64) {   // m tiles first (longer) for better tail packing
            A = Aall + (size_t)N_D * N_D + (size_t)by * 128 * N_M;
            K = N_M; crow = N_D + by * 128;
            Bh = Bt + (size_t)512 * N_D + (size_t)nb0 * K;
        } else {
            A = Aall + (size_t)(by - 64) * 128 * N_D;
            K = N_D; crow = (by - 64) * 128;
            Bh = Bt + (size_t)nb0 * K;
        }
    } else {
        K = Kin; crow = by * 128;
        A = Aall + (size_t)crow * K;
        Bh = Bt + (size_t)nb0 * K;
    }
    const int chunks = K >> 5;

    auto load_stage = [&](int stage, int c) {
        const int k0 = c << 5;
        const uint32_t sb = sbase + stage * STAGE_B2;
        #pragma unroll
        for (int i = 0; i < 2; i++) {
            int idx = tid + (i << 8);
            int row = idx >> 2, ch = idx & 3;
            uint32_t sw = (uint32_t)(ch ^ ((row >> 1) & 3));
            uint32_t off = row * 64 + (sw << 4);
            cpasync16(sb + off,          A  + (size_t)row * K + k0 + ch * 8);
            cpasync16(sb + TILE_B + off, Bh + (size_t)row * K + k0 + ch * 8);
        }
    };
    auto ldfrags = [&](uint32_t sb, int ks, uint32_t (*aF)[4], uint32_t (*bF)[2]) {
        #pragma unroll
        for (int mt = 0; mt < 2; mt++) {
            int row = wm * 32 + mt * 16 + (lid & 15);
            int ch  = ks * 2 + (lid >> 4);
            uint32_t off = row * 64 + ((uint32_t)(ch ^ ((row >> 1) & 3)) << 4);
            ldsm_x4(sb + off, aF[mt][0], aF[mt][1], aF[mt][2], aF[mt][3]);
        }
        #pragma unroll
        for (int nt2 = 0; nt2 < 4; nt2++) {
            int row = wn * 64 + nt2 * 16 + (lid & 7) + ((lid >> 4) << 3);
            int ch  = ks * 2 + ((lid >> 3) & 1);
            uint32_t off = row * 64 + ((uint32_t)(ch ^ ((row >> 1) & 3)) << 4);
            ldsm_x4(sb + TILE_B + off,
                    bF[2*nt2][0], bF[2*nt2][1], bF[2*nt2+1][0], bF[2*nt2+1][1]);
        }
    };

    float acc[2][8][4] = {};

    #pragma unroll
    for (int s = 0; s < GSTG - 1; s++) { load_stage(s, s); cp_commit(); }

    for (int c = 0; c < chunks; c++) {
        cp_wait<GSTG - 2>();
        __syncthreads();
        const int cl = c + GSTG - 1;
        if (cl < chunks) load_stage(cl % GSTG, cl);
        cp_commit();

        const uint32_t sb = sbase + (c % GSTG) * STAGE_B2;
        #pragma unroll
        for (int ks = 0; ks < 2; ks++) {
            uint32_t aF[2][4], bF[8][2];
            ldfrags(sb, ks, aF, bF);
            #pragma unroll
            for (int mt = 0; mt < 2; mt++)
                #pragma unroll
                for (int nt = 0; nt < 8; nt++)
                    mma16816(acc[mt][nt], aF[mt], bF[nt]);
        }
    }

    // ---- epilogue
    const int gid = lid >> 2, tig = lid & 3;
    if (mode == 0) {
        #pragma unroll
        for (int mt = 0; mt < 2; mt++) {
            #pragma unroll
            for (int nt = 0; nt < 8; nt++) {
                int r0  = crow + wm * 32 + mt * 16 + gid;
                int col = nb0 + wn * 64 + nt * 8 + tig * 2;
                *reinterpret_cast<__half2*>(g_Fh + (size_t)r0 * LDF + col) =
                    __floats2half2_rn(acc[mt][nt][0], acc[mt][nt][1]);
                *reinterpret_cast<__half2*>(g_Fh + (size_t)(r0 + 8) * LDF + col) =
                    __floats2half2_rn(acc[mt][nt][2], acc[mt][nt][3]);
            }
        }
    } else {
        #pragma unroll
        for (int mt = 0; mt < 2; mt++) {
            #pragma unroll
            for (int nt = 0; nt < 8; nt++) {
                int r0  = crow + wm * 32 + mt * 16 + gid;
                int col = nb0 + wn * 64 + nt * 8 + tig * 2;
                float2 bb = *reinterpret_cast<const float2*>(bias + col);
                float2 v0 = make_float2(acc[mt][nt][0] + bb.x, acc[mt][nt][1] + bb.y);
                float2 v1 = make_float2(acc[mt][nt][2] + bb.x, acc[mt][nt][3] + bb.y);
                *reinterpret_cast<float2*>(C + (size_t)r0 * HIDD + col)       = v0;
                *reinterpret_cast<float2*>(C + (size_t)(r0 + 8) * HIDD + col) = v1;
            }
        }
    }
}

// ---------------- pair scoring: warp per pair -------------------------------
__global__ void pair_kernel(const int* __restrict__ dis, const int* __restrict__ mir,
                            const float* __restrict__ Wp, const float* __restrict__ bp,
                            float* __restrict__ out, int P)
{
    int warp = (blockIdx.x * blockDim.x + threadIdx.x) >> 5;
    int lane = threadIdx.x & 31;
    if (warp >= P) return;
    int di = dis[warp];
    int mi = mir[warp];
    const float* hd = g_h + (size_t)di * HIDD;
    const float* hm = g_h + (size_t)mi * HIDD;
    float s = 0.f;
    #pragma unroll 4
    for (int c = lane; c < HIDD; c += 32) {
        float a = hd[c], b = hm[c];
        s += a * Wp[c] + b * Wp[HIDD + c] + (a * b) * Wp[2 * HIDD + c];
    }
    #pragma unroll
    for (int o = 16; o; o >>= 1) s += __shfl_xor_sync(0xffffffffu, s, o);
    if (lane == 0) out[warp] = 1.f / (1.f + expf(-(s + bp[0])));
}

// ---------------- launch ----------------------------------------------------
extern "C" void kernel_launch(void* const* d_in, const int* in_sizes, int n_in,
                              void* d_out, int out_size)
{
    const float* d_sim    = (const float*)d_in[0];
    const float* m_sim    = (const float*)d_in[1];
    const int*   src      = (const int*)  d_in[2];
    const int*   dst      = (const int*)  d_in[3];
    const int*   diseases = (const int*)  d_in[4];
    const int*   mirnas   = (const int*)  d_in[5];
    const float* Wd       = (const float*)d_in[6];
    const float* Wm       = (const float*)d_in[7];
    const float* Wf       = (const float*)d_in[8];
    const float* bf       = (const float*)d_in[9];
    const float* Wp       = (const float*)d_in[10];
    const float* bp       = (const float*)d_in[11];
    float*       out      = (float*)d_out;

    const int E = in_sizes[2];
    const int P = in_sizes[4];

    float* hbuf = nullptr;
    __half *Bt = nullptr, *Fh = nullptr, *Ah = nullptr;
    cudaGetSymbolAddress((void**)&hbuf, g_h);
    cudaGetSymbolAddress((void**)&Bt, g_Bt);
    cudaGetSymbolAddress((void**)&Fh, g_Fh);
    cudaGetSymbolAddress((void**)&Ah, g_Ah);

    cudaFuncSetAttribute(gemm_core, cudaFuncAttributeMaxDynamicSharedMemorySize, GEMM_SMEM);

    // launches ordered so gemm_core(dm) is #4 (the one ncu profiles)
    cvtA_kernel<<<(N_M * N_M / 4 + 255) / 256, 256>>>(
        m_sim, Ah + (size_t)N_D * N_D, N_M * N_M / 4);                          // 1
    cvtA_kernel<<<(N_D * N_D / 4 + 255) / 256, 256>>>(d_sim, Ah, N_D * N_D / 4);// 2
    cvtBT_all<<<dim3(HIDD / 32, N_M / 32, 3), dim3(32, 8)>>>(Wd, Wm, Wf, Bt);   // 3
    gemm_core<<<dim3(4, 96), 256, GEMM_SMEM>>>(
        Ah, Bt, 0, nullptr, nullptr, 0);                                        // 4 <- profiled
    zero_kernel<<<(NN + 255) / 256, 256>>>();                                   // 5
    deg_kernel<<<(E + 255) / 256, 256>>>(dst, E);                               // 6
    normscan_kernel<<<1, 1024>>>();                                             // 7
    fill_kernel<<<(E + 255) / 256, 256>>>(src, dst, E);                         // 8

    // ---- K hops of normalized gather-sum (fp16 feat, fp32 accumulate)
    for (int hop = 0; hop < KHOP; hop++)
        hop_kernel<<<NN, 256>>>(hop * HIDD, (hop + 1) * HIDD);

    // ---- h = feat @ Wf + bf
    gemm_core<<<dim3(4, 96), 256, GEMM_SMEM>>>(
        Fh, Bt + (size_t)512 * (N_D + N_M), LDF, hbuf, bf, 1);

    // ---- pair prediction with sigmoid
    pair_kernel<<<(P * 32 + 255) / 256, 256>>>(diseases, mirnas, Wp, bp, out, P);
    (void)n_in; (void)out_size;
}